// round 9
// baseline (speedup 1.0000x reference)
#include <cuda_runtime.h>
#include <cstdint>

#define NN 65536
#define DD 64
#define EE 1048576
#define SS 1024

typedef unsigned long long u64;

// Scratch (device globals — no allocation allowed)
__device__ float g_y[NN * DD];
__device__ float g_z2[NN * DD];
__device__ float g_h[NN * DD];
// per-layer stats: layer l uses [l*256 .. l*256+256):
//   [ +0:+64) sum1, [+64:+128) sumsq1   (gemm1 output stats)
//   [+128:+192) sum2, [+192:+256) sumsq2 (gemm2 output stats)
__device__ float g_stats[512];
__device__ int   g_deg[NN];
__device__ int   g_rowloc[NN + 1];   // block-local exclusive prefix
__device__ int   g_fill[NN];
__device__ int   g_csr[EE];
__device__ int   g_bsum[256];
__device__ int   g_boff[257];

// ---------------------------------------------------------------------------
// zero: out, g_deg, g_stats, g_rowloc[NN]; 128 blocks x 256 threads
__global__ void init_kernel(float* __restrict__ out) {
    int i = blockIdx.x * 256 + threadIdx.x;            // 0 .. 32767
    ((float4*)out)[i] = make_float4(0.f, 0.f, 0.f, 0.f); // 32768 float4 = SS*128
    if (i < NN / 4) ((int4*)g_deg)[i] = make_int4(0, 0, 0, 0);
    if (i < 512) g_stats[i] = 0.f;
    if (i == 0) g_rowloc[NN] = 0;
}

__global__ void count_kernel(const int* __restrict__ ei) {
    int e = blockIdx.x * 256 + threadIdx.x;
    atomicAdd(&g_deg[__ldg(ei + EE + e)], 1);
}

// per-block (256 elems) exclusive scan + block totals
__global__ void scan1_kernel() {
    __shared__ int wsum[8];
    int t = threadIdx.x;
    int i = blockIdx.x * 256 + t;
    int v = g_deg[i];
    int inc = v;
    #pragma unroll
    for (int o = 1; o < 32; o <<= 1) {
        int n = __shfl_up_sync(0xffffffffu, inc, o);
        if ((t & 31) >= o) inc += n;
    }
    if ((t & 31) == 31) wsum[t >> 5] = inc;
    __syncthreads();
    if (t < 8) {
        int w = wsum[t];
        #pragma unroll
        for (int o = 1; o < 8; o <<= 1) {
            int n = __shfl_up_sync(0xffu, w, o);
            if (t >= o) w += n;
        }
        wsum[t] = w;
    }
    __syncthreads();
    int warpoff = (t >= 32) ? wsum[(t >> 5) - 1] : 0;
    int loc = inc - v + warpoff;
    g_rowloc[i] = loc;
    g_fill[i]   = loc;
    if (t == 0) g_bsum[blockIdx.x] = wsum[7];
}

// exclusive scan of the 256 block totals
__global__ void scan2_kernel() {
    __shared__ int wsum[8];
    int t = threadIdx.x;
    int v = g_bsum[t];
    int inc = v;
    #pragma unroll
    for (int o = 1; o < 32; o <<= 1) {
        int n = __shfl_up_sync(0xffffffffu, inc, o);
        if ((t & 31) >= o) inc += n;
    }
    if ((t & 31) == 31) wsum[t >> 5] = inc;
    __syncthreads();
    if (t < 8) {
        int w = wsum[t];
        #pragma unroll
        for (int o = 1; o < 8; o <<= 1) {
            int n = __shfl_up_sync(0xffu, w, o);
            if (t >= o) w += n;
        }
        wsum[t] = w;
    }
    __syncthreads();
    int warpoff = (t >= 32) ? wsum[(t >> 5) - 1] : 0;
    g_boff[t] = inc - v + warpoff;
    if (t == 0) g_boff[256] = EE;
}

__global__ void fill_kernel(const int* __restrict__ ei) {
    int e = blockIdx.x * 256 + threadIdx.x;
    int s = __ldg(ei + e);
    int d = __ldg(ei + EE + e);
    int p = atomicAdd(&g_fill[d], 1) + g_boff[d >> 8];
    g_csr[p] = s;
}

// ---------------------------------------------------------------------------
// Fused: CSR gather -> z tile in smem -> z @ W1 + b1 -> g_y, + column stats.
// 128 threads, 512 blocks, 128 nodes/block.
__global__ void __launch_bounds__(128)
gather_gemm_kernel(const float* __restrict__ x, const float* __restrict__ eps,
                   const float* __restrict__ W, const float* __restrict__ bias,
                   int layer) {
    const float* h = layer ? g_h : x;
    __shared__ float4 zs4[128 * 16];  // 32 KB, [row][c4 ^ (row>>3)]
    __shared__ float4 ws4[64 * 16];   // 16 KB
    int t = threadIdx.x;

    #pragma unroll
    for (int p = 0; p < 8; p++)
        ws4[t + p * 128] = __ldg(((const float4*)W) + t + p * 128);

    // gather phase: 16 threads per node, 8 nodes per iteration
    {
        const float4* h4 = (const float4*)h;
        float se = 1.0f + __ldg(eps + layer);
        int gq = t & 15, gn = t >> 4;
        #pragma unroll 1
        for (int it = 0; it < 16; it++) {
            int node = blockIdx.x * 128 + it * 8 + gn;
            int e0 = g_rowloc[node] + g_boff[node >> 8];
            int e1 = g_rowloc[node + 1] + g_boff[(node + 1) >> 8];
            float4 acc = __ldg(h4 + node * 16 + gq);
            acc.x *= se; acc.y *= se; acc.z *= se; acc.w *= se;
            int e = e0;
            for (; e + 4 <= e1; e += 4) {
                int a0 = g_csr[e],     a1 = g_csr[e + 1];
                int a2 = g_csr[e + 2], a3 = g_csr[e + 3];
                float4 v0 = __ldg(h4 + a0 * 16 + gq);
                float4 v1 = __ldg(h4 + a1 * 16 + gq);
                float4 v2 = __ldg(h4 + a2 * 16 + gq);
                float4 v3 = __ldg(h4 + a3 * 16 + gq);
                acc.x += (v0.x + v1.x) + (v2.x + v3.x);
                acc.y += (v0.y + v1.y) + (v2.y + v3.y);
                acc.z += (v0.z + v1.z) + (v2.z + v3.z);
                acc.w += (v0.w + v1.w) + (v2.w + v3.w);
            }
            for (; e < e1; e++) {
                int a = g_csr[e];
                float4 v = __ldg(h4 + a * 16 + gq);
                acc.x += v.x; acc.y += v.y; acc.z += v.z; acc.w += v.w;
            }
            zs4[(it * 8 + gn) * 16 + (gq ^ it)] = acc;  // row>>3 == it
        }
    }
    __syncthreads();

    int tr = t >> 3, tc = t & 7;
    int rbase = tr * 8;
    u64 acc2[8][4];
    #pragma unroll
    for (int i = 0; i < 8; i++)
        #pragma unroll
        for (int j = 0; j < 4; j++) acc2[i][j] = 0ull;

    #pragma unroll
    for (int kc = 0; kc < 16; kc++) {
        u64 b2[4][4];
        #pragma unroll
        for (int kk = 0; kk < 4; kk++) {
            const ulonglong2* wp = (const ulonglong2*)(ws4 + (kc * 4 + kk) * 16 + tc * 2);
            ulonglong2 p0 = wp[0];
            ulonglong2 p1 = wp[1];
            b2[kk][0] = p0.x; b2[kk][1] = p0.y;
            b2[kk][2] = p1.x; b2[kk][3] = p1.y;
        }
        #pragma unroll
        for (int ri = 0; ri < 8; ri++) {
            float4 a = zs4[(rbase + ri) * 16 + (kc ^ tr)];
            u64 d0, d1, d2, d3;
            asm("mov.b64 %0, {%1, %1};" : "=l"(d0) : "r"(__float_as_uint(a.x)));
            asm("mov.b64 %0, {%1, %1};" : "=l"(d1) : "r"(__float_as_uint(a.y)));
            asm("mov.b64 %0, {%1, %1};" : "=l"(d2) : "r"(__float_as_uint(a.z)));
            asm("mov.b64 %0, {%1, %1};" : "=l"(d3) : "r"(__float_as_uint(a.w)));
            #pragma unroll
            for (int j = 0; j < 4; j++) {
                asm("fma.rn.f32x2 %0, %1, %2, %0;" : "+l"(acc2[ri][j]) : "l"(d0), "l"(b2[0][j]));
                asm("fma.rn.f32x2 %0, %1, %2, %0;" : "+l"(acc2[ri][j]) : "l"(d1), "l"(b2[1][j]));
                asm("fma.rn.f32x2 %0, %1, %2, %0;" : "+l"(acc2[ri][j]) : "l"(d2), "l"(b2[2][j]));
                asm("fma.rn.f32x2 %0, %1, %2, %0;" : "+l"(acc2[ri][j]) : "l"(d3), "l"(b2[3][j]));
            }
        }
    }

    float4 bb0 = __ldg(((const float4*)bias) + tc * 2);
    float4 bb1 = __ldg(((const float4*)bias) + tc * 2 + 1);
    float bbv[8] = {bb0.x, bb0.y, bb0.z, bb0.w, bb1.x, bb1.y, bb1.z, bb1.w};
    float cs[8], cq[8];
    #pragma unroll
    for (int j = 0; j < 8; j++) { cs[j] = 0.f; cq[j] = 0.f; }
    #pragma unroll
    for (int ri = 0; ri < 8; ri++) {
        int row = rbase + ri;
        float o[8];
        #pragma unroll
        for (int j = 0; j < 4; j++) {
            unsigned lo, hi;
            asm("mov.b64 {%0, %1}, %2;" : "=r"(lo), "=r"(hi) : "l"(acc2[ri][j]));
            o[2 * j]     = __uint_as_float(lo) + bbv[2 * j];
            o[2 * j + 1] = __uint_as_float(hi) + bbv[2 * j + 1];
        }
        float* op = g_y + ((size_t)blockIdx.x * 128 + row) * DD + tc * 8;
        *(float4*)op       = make_float4(o[0], o[1], o[2], o[3]);
        *(float4*)(op + 4) = make_float4(o[4], o[5], o[6], o[7]);
        #pragma unroll
        for (int j = 0; j < 8; j++) {
            cs[j] += o[j];
            cq[j] += o[j] * o[j];
        }
    }

    __syncthreads();
    float* red = (float*)zs4;
    #pragma unroll
    for (int j = 0; j < 8; j++) {
        red[tr * 64 + tc * 8 + j]        = cs[j];
        red[1024 + tr * 64 + tc * 8 + j] = cq[j];
    }
    __syncthreads();
    if (t < 64) {
        float s1 = 0.f, s2 = 0.f;
        #pragma unroll
        for (int g = 0; g < 16; g++) {
            s1 += red[g * 64 + t];
            s2 += red[1024 + g * 64 + t];
        }
        atomicAdd(&g_stats[layer * 256 + t], s1);
        atomicAdd(&g_stats[layer * 256 + 64 + t], s2);
    }
}

// ---------------------------------------------------------------------------
// g_z2 = relu(bn1(g_y)) @ W2 + b2, with per-thread BN coefficients from
// g_stats[layer*256 .. +128); output stats -> g_stats[layer*256+128 .. +256).
__global__ void __launch_bounds__(128)
bn_gemm_kernel(const float* __restrict__ W, const float* __restrict__ bias,
               const float* __restrict__ gamma, const float* __restrict__ beta,
               int layer) {
    __shared__ float4 zs4[128 * 16];
    __shared__ float4 ws4[64 * 16];
    int t = threadIdx.x;

    #pragma unroll
    for (int p = 0; p < 8; p++)
        ws4[t + p * 128] = __ldg(((const float4*)W) + t + p * 128);

    int c4 = t & 15;
    int c0 = c4 * 4;
    float scv[4], shv[4];
    #pragma unroll
    for (int j = 0; j < 4; j++) {
        float mu  = g_stats[layer * 256 + c0 + j]      * (1.0f / NN);
        float var = g_stats[layer * 256 + 64 + c0 + j] * (1.0f / NN) - mu * mu;
        float s = __ldg(gamma + c0 + j) * rsqrtf(var + 1e-5f);
        scv[j] = s;
        shv[j] = __ldg(beta + c0 + j) - mu * s;
    }
    const float4* in4 = (const float4*)(g_y + (size_t)blockIdx.x * 128 * DD);
    #pragma unroll
    for (int p = 0; p < 16; p++) {
        int row = (t >> 4) + p * 8;
        float4 v = __ldg(in4 + row * 16 + c4);
        v.x = fmaxf(fmaf(v.x, scv[0], shv[0]), 0.f);
        v.y = fmaxf(fmaf(v.y, scv[1], shv[1]), 0.f);
        v.z = fmaxf(fmaf(v.z, scv[2], shv[2]), 0.f);
        v.w = fmaxf(fmaf(v.w, scv[3], shv[3]), 0.f);
        zs4[row * 16 + (c4 ^ p)] = v;
    }
    __syncthreads();

    int tr = t >> 3, tc = t & 7;
    int rbase = tr * 8;
    u64 acc2[8][4];
    #pragma unroll
    for (int i = 0; i < 8; i++)
        #pragma unroll
        for (int j = 0; j < 4; j++) acc2[i][j] = 0ull;

    #pragma unroll
    for (int kc = 0; kc < 16; kc++) {
        u64 b2[4][4];
        #pragma unroll
        for (int kk = 0; kk < 4; kk++) {
            const ulonglong2* wp = (const ulonglong2*)(ws4 + (kc * 4 + kk) * 16 + tc * 2);
            ulonglong2 p0 = wp[0];
            ulonglong2 p1 = wp[1];
            b2[kk][0] = p0.x; b2[kk][1] = p0.y;
            b2[kk][2] = p1.x; b2[kk][3] = p1.y;
        }
        #pragma unroll
        for (int ri = 0; ri < 8; ri++) {
            float4 a = zs4[(rbase + ri) * 16 + (kc ^ tr)];
            u64 d0, d1, d2, d3;
            asm("mov.b64 %0, {%1, %1};" : "=l"(d0) : "r"(__float_as_uint(a.x)));
            asm("mov.b64 %0, {%1, %1};" : "=l"(d1) : "r"(__float_as_uint(a.y)));
            asm("mov.b64 %0, {%1, %1};" : "=l"(d2) : "r"(__float_as_uint(a.z)));
            asm("mov.b64 %0, {%1, %1};" : "=l"(d3) : "r"(__float_as_uint(a.w)));
            #pragma unroll
            for (int j = 0; j < 4; j++) {
                asm("fma.rn.f32x2 %0, %1, %2, %0;" : "+l"(acc2[ri][j]) : "l"(d0), "l"(b2[0][j]));
                asm("fma.rn.f32x2 %0, %1, %2, %0;" : "+l"(acc2[ri][j]) : "l"(d1), "l"(b2[1][j]));
                asm("fma.rn.f32x2 %0, %1, %2, %0;" : "+l"(acc2[ri][j]) : "l"(d2), "l"(b2[2][j]));
                asm("fma.rn.f32x2 %0, %1, %2, %0;" : "+l"(acc2[ri][j]) : "l"(d3), "l"(b2[3][j]));
            }
        }
    }

    float4 bb0 = __ldg(((const float4*)bias) + tc * 2);
    float4 bb1 = __ldg(((const float4*)bias) + tc * 2 + 1);
    float bbv[8] = {bb0.x, bb0.y, bb0.z, bb0.w, bb1.x, bb1.y, bb1.z, bb1.w};
    float cs[8], cq[8];
    #pragma unroll
    for (int j = 0; j < 8; j++) { cs[j] = 0.f; cq[j] = 0.f; }
    #pragma unroll
    for (int ri = 0; ri < 8; ri++) {
        int row = rbase + ri;
        float o[8];
        #pragma unroll
        for (int j = 0; j < 4; j++) {
            unsigned lo, hi;
            asm("mov.b64 {%0, %1}, %2;" : "=r"(lo), "=r"(hi) : "l"(acc2[ri][j]));
            o[2 * j]     = __uint_as_float(lo) + bbv[2 * j];
            o[2 * j + 1] = __uint_as_float(hi) + bbv[2 * j + 1];
        }
        float* op = g_z2 + ((size_t)blockIdx.x * 128 + row) * DD + tc * 8;
        *(float4*)op       = make_float4(o[0], o[1], o[2], o[3]);
        *(float4*)(op + 4) = make_float4(o[4], o[5], o[6], o[7]);
        #pragma unroll
        for (int j = 0; j < 8; j++) {
            cs[j] += o[j];
            cq[j] += o[j] * o[j];
        }
    }

    __syncthreads();
    float* red = (float*)zs4;
    #pragma unroll
    for (int j = 0; j < 8; j++) {
        red[tr * 64 + tc * 8 + j]        = cs[j];
        red[1024 + tr * 64 + tc * 8 + j] = cq[j];
    }
    __syncthreads();
    if (t < 64) {
        float s1 = 0.f, s2 = 0.f;
        #pragma unroll
        for (int g = 0; g < 16; g++) {
            s1 += red[g * 64 + t];
            s2 += red[1024 + g * 64 + t];
        }
        atomicAdd(&g_stats[layer * 256 + 128 + t], s1);
        atomicAdd(&g_stats[layer * 256 + 192 + t], s2);
    }
}

// ---------------------------------------------------------------------------
// h = relu(bn2(g_z2)); segment-max into out[:, layer*64 : layer*64+64]
__global__ void __launch_bounds__(256)
apply_kernel(const int* __restrict__ n2s, float* __restrict__ out,
             const float* __restrict__ gamma, const float* __restrict__ beta,
             int layer) {
    __shared__ float red[16 * DD];
    __shared__ float ssc[64], ssh[64];
    int t = threadIdx.x, b = blockIdx.x;
    if (t < 64) {
        float mu  = g_stats[layer * 256 + 128 + t] * (1.0f / NN);
        float var = g_stats[layer * 256 + 192 + t] * (1.0f / NN) - mu * mu;
        float s = __ldg(gamma + t) * rsqrtf(var + 1e-5f);
        ssc[t] = s;
        ssh[t] = __ldg(beta + t) - mu * s;
    }
    __syncthreads();

    int g = t >> 4, q = t & 15;
    int c0 = q * 4;
    float s0 = ssc[c0], s1 = ssc[c0 + 1], s2 = ssc[c0 + 2], s3 = ssc[c0 + 3];
    float h0 = ssh[c0], h1 = ssh[c0 + 1], h2 = ssh[c0 + 2], h3 = ssh[c0 + 3];

    float4 m = make_float4(0.f, 0.f, 0.f, 0.f);
    #pragma unroll
    for (int p = 0; p < 4; p++) {
        int row = b * 64 + p * 16 + g;
        float4 v = *(const float4*)(g_z2 + (size_t)row * DD + c0);
        v.x = fmaxf(fmaf(v.x, s0, h0), 0.f);
        v.y = fmaxf(fmaf(v.y, s1, h1), 0.f);
        v.z = fmaxf(fmaf(v.z, s2, h2), 0.f);
        v.w = fmaxf(fmaf(v.w, s3, h3), 0.f);
        *(float4*)(g_h + (size_t)row * DD + c0) = v;
        m.x = fmaxf(m.x, v.x); m.y = fmaxf(m.y, v.y);
        m.z = fmaxf(m.z, v.z); m.w = fmaxf(m.w, v.w);
    }
    red[g * DD + c0 + 0] = m.x; red[g * DD + c0 + 1] = m.y;
    red[g * DD + c0 + 2] = m.z; red[g * DD + c0 + 3] = m.w;
    __syncthreads();

    if (t < DD) {
        float mv = red[t];
        #pragma unroll
        for (int gg = 1; gg < 16; gg++) mv = fmaxf(mv, red[gg * DD + t]);
        int sA = __ldg(n2s + b * 64), sB = __ldg(n2s + b * 64 + 63);
        if (sA == sB) {
            unsigned* p = (unsigned*)(out + (size_t)sA * 128 + layer * 64 + t);
            asm volatile("red.global.max.u32 [%0], %1;"
                         :: "l"(p), "r"(__float_as_uint(mv)) : "memory");
        } else {
            for (int r = 0; r < 64; r++) {
                int seg = __ldg(n2s + b * 64 + r);
                float v = g_h[((size_t)b * 64 + r) * DD + t];
                unsigned* p = (unsigned*)(out + (size_t)seg * 128 + layer * 64 + t);
                asm volatile("red.global.max.u32 [%0], %1;"
                             :: "l"(p), "r"(__float_as_uint(v)) : "memory");
            }
        }
    }
}

// ---------------------------------------------------------------------------
extern "C" void kernel_launch(void* const* d_in, const int* in_sizes, int n_in,
                              void* d_out, int out_size) {
    const float* x   = (const float*)d_in[0];
    const int*   ei  = (const int*)d_in[1];
    const int*   n2s = (const int*)d_in[2];
    const float* eps = (const float*)d_in[3];
    const float* W1  = (const float*)d_in[4];
    const float* b1  = (const float*)d_in[5];
    const float* gm  = (const float*)d_in[6];
    const float* bm  = (const float*)d_in[7];
    const float* W2  = (const float*)d_in[8];
    const float* b2  = (const float*)d_in[9];
    const float* go  = (const float*)d_in[10];
    const float* bo  = (const float*)d_in[11];
    float* out = (float*)d_out;

    init_kernel<<<128, 256>>>(out);
    count_kernel<<<EE / 256, 256>>>(ei);
    scan1_kernel<<<NN / 256, 256>>>();
    scan2_kernel<<<1, 256>>>();
    fill_kernel<<<EE / 256, 256>>>(ei);

    for (int l = 0; l < 2; l++) {
        gather_gemm_kernel<<<NN / 128, 128>>>(x, eps, W1 + l * DD * DD,
                                              b1 + l * DD, l);
        bn_gemm_kernel<<<NN / 128, 128>>>(W2 + l * DD * DD, b2 + l * DD,
                                          gm + l * DD, bm + l * DD, l);
        apply_kernel<<<NN / 64, 256>>>(n2s, out, go + l * DD, bo + l * DD, l);
    }
}

// round 10
// speedup vs baseline: 1.6248x; 1.6248x over previous
#include <cuda_runtime.h>
#include <cstdint>

#define NN 65536
#define DD 64
#define EE 1048576
#define SS 1024

typedef unsigned long long u64;

// Scratch (device globals — no allocation allowed)
__device__ float g_y[NN * DD];
__device__ float g_z2[NN * DD];   // holds z (gather out / gemm1 in), then z2 (gemm2 out)
__device__ float g_h[NN * DD];
// per-layer stats: layer l uses [l*256 .. l*256+256):
//   [+0:+64) sum1, [+64:+128) sumsq1   (gemm1 output stats)
//   [+128:+192) sum2, [+192:+256) sumsq2 (gemm2 output stats)
__device__ float g_stats[512];
__device__ int   g_deg[NN];
__device__ int   g_rowloc[NN + 1];   // block-local exclusive prefix
__device__ int   g_fill[NN];
__device__ int   g_csr[EE];
__device__ int   g_bsum[256];
__device__ int   g_boff[257];

// ---------------------------------------------------------------------------
// zero: out, g_deg, g_stats, g_rowloc[NN]; 128 blocks x 256 threads
__global__ void init_kernel(float* __restrict__ out) {
    int i = blockIdx.x * 256 + threadIdx.x;              // 0 .. 32767
    ((float4*)out)[i] = make_float4(0.f, 0.f, 0.f, 0.f); // 32768 float4 = SS*128
    if (i < NN / 4) ((int4*)g_deg)[i] = make_int4(0, 0, 0, 0);
    if (i < 512) g_stats[i] = 0.f;
    if (i == 0) g_rowloc[NN] = 0;
}

__global__ void count_kernel(const int* __restrict__ ei) {
    int e = blockIdx.x * 256 + threadIdx.x;
    atomicAdd(&g_deg[__ldg(ei + EE + e)], 1);
}

// per-block (256 elems) exclusive scan + block totals
__global__ void scan1_kernel() {
    __shared__ int wsum[8];
    int t = threadIdx.x;
    int i = blockIdx.x * 256 + t;
    int v = g_deg[i];
    int inc = v;
    #pragma unroll
    for (int o = 1; o < 32; o <<= 1) {
        int n = __shfl_up_sync(0xffffffffu, inc, o);
        if ((t & 31) >= o) inc += n;
    }
    if ((t & 31) == 31) wsum[t >> 5] = inc;
    __syncthreads();
    if (t < 8) {
        int w = wsum[t];
        #pragma unroll
        for (int o = 1; o < 8; o <<= 1) {
            int n = __shfl_up_sync(0xffu, w, o);
            if (t >= o) w += n;
        }
        wsum[t] = w;
    }
    __syncthreads();
    int warpoff = (t >= 32) ? wsum[(t >> 5) - 1] : 0;
    int loc = inc - v + warpoff;
    g_rowloc[i] = loc;
    g_fill[i]   = loc;
    if (t == 0) g_bsum[blockIdx.x] = wsum[7];
}

// exclusive scan of the 256 block totals
__global__ void scan2_kernel() {
    __shared__ int wsum[8];
    int t = threadIdx.x;
    int v = g_bsum[t];
    int inc = v;
    #pragma unroll
    for (int o = 1; o < 32; o <<= 1) {
        int n = __shfl_up_sync(0xffffffffu, inc, o);
        if ((t & 31) >= o) inc += n;
    }
    if ((t & 31) == 31) wsum[t >> 5] = inc;
    __syncthreads();
    if (t < 8) {
        int w = wsum[t];
        #pragma unroll
        for (int o = 1; o < 8; o <<= 1) {
            int n = __shfl_up_sync(0xffu, w, o);
            if (t >= o) w += n;
        }
        wsum[t] = w;
    }
    __syncthreads();
    int warpoff = (t >= 32) ? wsum[(t >> 5) - 1] : 0;
    g_boff[t] = inc - v + warpoff;
    if (t == 0) g_boff[256] = EE;
}

__global__ void fill_kernel(const int* __restrict__ ei) {
    int e = blockIdx.x * 256 + threadIdx.x;
    int s = __ldg(ei + e);
    int d = __ldg(ei + EE + e);
    int p = atomicAdd(&g_fill[d], 1) + g_boff[d >> 8];
    g_csr[p] = s;
}

// ---------------------------------------------------------------------------
// z[n] = (1+eps)*h[n] + sum over CSR neighbors -> g_z2.
// 256 threads, 16 threads/node, 16 nodes/block (high-occupancy, latency-bound).
__global__ void __launch_bounds__(256)
gather_kernel(const float* __restrict__ x, const float* __restrict__ eps, int layer) {
    const float* h = layer ? g_h : x;
    const float4* h4 = (const float4*)h;
    int t = threadIdx.x;
    int n = blockIdx.x * 16 + (t >> 4);
    int q = t & 15;
    int e0 = g_rowloc[n] + g_boff[n >> 8];
    int e1 = g_rowloc[n + 1] + g_boff[(n + 1) >> 8];
    float se = 1.0f + __ldg(eps + layer);
    float4 acc = __ldg(h4 + n * 16 + q);
    acc.x *= se; acc.y *= se; acc.z *= se; acc.w *= se;
    int e = e0;
    for (; e + 4 <= e1; e += 4) {
        int a0 = g_csr[e],     a1 = g_csr[e + 1];
        int a2 = g_csr[e + 2], a3 = g_csr[e + 3];
        float4 v0 = __ldg(h4 + a0 * 16 + q);
        float4 v1 = __ldg(h4 + a1 * 16 + q);
        float4 v2 = __ldg(h4 + a2 * 16 + q);
        float4 v3 = __ldg(h4 + a3 * 16 + q);
        acc.x += (v0.x + v1.x) + (v2.x + v3.x);
        acc.y += (v0.y + v1.y) + (v2.y + v3.y);
        acc.z += (v0.z + v1.z) + (v2.z + v3.z);
        acc.w += (v0.w + v1.w) + (v2.w + v3.w);
    }
    for (; e < e1; e++) {
        int a = g_csr[e];
        float4 v = __ldg(h4 + a * 16 + q);
        acc.x += v.x; acc.y += v.y; acc.z += v.z; acc.w += v.w;
    }
    ((float4*)g_z2)[n * 16 + q] = acc;
}

// ---------------------------------------------------------------------------
// out = in @ W + b with f32x2 packed FMA mainloop + fused column stats.
// BN=false: g_z2 -> g_y, stats -> [layer*256 + 0/64)
// BN=true:  in := relu(bn1(g_y)) on load (coeffs from [layer*256+0/64)),
//           g_y -> g_z2, stats -> [layer*256 + 128/192)
template <bool BN>
__global__ void __launch_bounds__(128)
gemm_kernel(const float* __restrict__ W, const float* __restrict__ bias,
            const float* __restrict__ gamma, const float* __restrict__ beta,
            int layer) {
    const float* in = BN ? g_y : g_z2;
    float* out      = BN ? g_z2 : g_y;
    __shared__ float4 zs4[128 * 16];  // 32 KB, [row][c4 ^ (row>>3)]
    __shared__ float4 ws4[64 * 16];   // 16 KB
    int t = threadIdx.x;

    #pragma unroll
    for (int p = 0; p < 8; p++)
        ws4[t + p * 128] = __ldg(((const float4*)W) + t + p * 128);

    int c4 = t & 15;
    float4 sc, sh;
    if (BN) {
        int c0 = c4 * 4;
        float scv[4], shv[4];
        #pragma unroll
        for (int j = 0; j < 4; j++) {
            float mu  = g_stats[layer * 256 + c0 + j]      * (1.0f / NN);
            float var = g_stats[layer * 256 + 64 + c0 + j] * (1.0f / NN) - mu * mu;
            float s = __ldg(gamma + c0 + j) * rsqrtf(var + 1e-5f);
            scv[j] = s;
            shv[j] = __ldg(beta + c0 + j) - mu * s;
        }
        sc = make_float4(scv[0], scv[1], scv[2], scv[3]);
        sh = make_float4(shv[0], shv[1], shv[2], shv[3]);
    }
    const float4* in4 = (const float4*)(in + (size_t)blockIdx.x * 128 * DD);
    #pragma unroll
    for (int p = 0; p < 16; p++) {
        int row = (t >> 4) + p * 8;
        float4 v = __ldg(in4 + row * 16 + c4);
        if (BN) {
            v.x = fmaxf(fmaf(v.x, sc.x, sh.x), 0.f);
            v.y = fmaxf(fmaf(v.y, sc.y, sh.y), 0.f);
            v.z = fmaxf(fmaf(v.z, sc.z, sh.z), 0.f);
            v.w = fmaxf(fmaf(v.w, sc.w, sh.w), 0.f);
        }
        zs4[row * 16 + (c4 ^ p)] = v;   // row>>3 == p
    }
    __syncthreads();

    int tr = t >> 3, tc = t & 7;
    int rbase = tr * 8;
    u64 acc2[8][4];
    #pragma unroll
    for (int i = 0; i < 8; i++)
        #pragma unroll
        for (int j = 0; j < 4; j++) acc2[i][j] = 0ull;

    #pragma unroll
    for (int kc = 0; kc < 16; kc++) {
        u64 b2[4][4];
        #pragma unroll
        for (int kk = 0; kk < 4; kk++) {
            const ulonglong2* wp = (const ulonglong2*)(ws4 + (kc * 4 + kk) * 16 + tc * 2);
            ulonglong2 p0 = wp[0];
            ulonglong2 p1 = wp[1];
            b2[kk][0] = p0.x; b2[kk][1] = p0.y;
            b2[kk][2] = p1.x; b2[kk][3] = p1.y;
        }
        #pragma unroll
        for (int ri = 0; ri < 8; ri++) {
            float4 a = zs4[(rbase + ri) * 16 + (kc ^ tr)];  // row>>3 == tr
            u64 d0, d1, d2, d3;
            asm("mov.b64 %0, {%1, %1};" : "=l"(d0) : "r"(__float_as_uint(a.x)));
            asm("mov.b64 %0, {%1, %1};" : "=l"(d1) : "r"(__float_as_uint(a.y)));
            asm("mov.b64 %0, {%1, %1};" : "=l"(d2) : "r"(__float_as_uint(a.z)));
            asm("mov.b64 %0, {%1, %1};" : "=l"(d3) : "r"(__float_as_uint(a.w)));
            #pragma unroll
            for (int j = 0; j < 4; j++) {
                asm("fma.rn.f32x2 %0, %1, %2, %0;" : "+l"(acc2[ri][j]) : "l"(d0), "l"(b2[0][j]));
                asm("fma.rn.f32x2 %0, %1, %2, %0;" : "+l"(acc2[ri][j]) : "l"(d1), "l"(b2[1][j]));
                asm("fma.rn.f32x2 %0, %1, %2, %0;" : "+l"(acc2[ri][j]) : "l"(d2), "l"(b2[2][j]));
                asm("fma.rn.f32x2 %0, %1, %2, %0;" : "+l"(acc2[ri][j]) : "l"(d3), "l"(b2[3][j]));
            }
        }
    }

    float4 bb0 = __ldg(((const float4*)bias) + tc * 2);
    float4 bb1 = __ldg(((const float4*)bias) + tc * 2 + 1);
    float bbv[8] = {bb0.x, bb0.y, bb0.z, bb0.w, bb1.x, bb1.y, bb1.z, bb1.w};
    float cs[8], cq[8];
    #pragma unroll
    for (int j = 0; j < 8; j++) { cs[j] = 0.f; cq[j] = 0.f; }
    #pragma unroll
    for (int ri = 0; ri < 8; ri++) {
        int row = rbase + ri;
        float o[8];
        #pragma unroll
        for (int j = 0; j < 4; j++) {
            unsigned lo, hi;
            asm("mov.b64 {%0, %1}, %2;" : "=r"(lo), "=r"(hi) : "l"(acc2[ri][j]));
            o[2 * j]     = __uint_as_float(lo) + bbv[2 * j];
            o[2 * j + 1] = __uint_as_float(hi) + bbv[2 * j + 1];
        }
        float* op = out + ((size_t)blockIdx.x * 128 + row) * DD + tc * 8;
        *(float4*)op       = make_float4(o[0], o[1], o[2], o[3]);
        *(float4*)(op + 4) = make_float4(o[4], o[5], o[6], o[7]);
        #pragma unroll
        for (int j = 0; j < 8; j++) {
            cs[j] += o[j];
            cq[j] += o[j] * o[j];
        }
    }

    __syncthreads();  // reuse zs4 as reduction buffer
    float* red = (float*)zs4;
    #pragma unroll
    for (int j = 0; j < 8; j++) {
        red[tr * 64 + tc * 8 + j]        = cs[j];
        red[1024 + tr * 64 + tc * 8 + j] = cq[j];
    }
    __syncthreads();
    if (t < 64) {
        float s1 = 0.f, s2 = 0.f;
        #pragma unroll
        for (int g = 0; g < 16; g++) {
            s1 += red[g * 64 + t];
            s2 += red[1024 + g * 64 + t];
        }
        int off = layer * 256 + (BN ? 128 : 0);
        atomicAdd(&g_stats[off + t], s1);
        atomicAdd(&g_stats[off + 64 + t], s2);
    }
}

// ---------------------------------------------------------------------------
// h = relu(bn2(g_z2)); segment-max into out[:, layer*64 : layer*64+64].
// LAST template arg: skip the g_h write on the final layer (h unused).
template <bool LAST>
__global__ void __launch_bounds__(256)
apply_kernel(const int* __restrict__ n2s, float* __restrict__ out,
             const float* __restrict__ gamma, const float* __restrict__ beta,
             int layer) {
    __shared__ float red[16 * DD];
    __shared__ float ssc[64], ssh[64];
    int t = threadIdx.x, b = blockIdx.x;
    if (t < 64) {
        float mu  = g_stats[layer * 256 + 128 + t] * (1.0f / NN);
        float var = g_stats[layer * 256 + 192 + t] * (1.0f / NN) - mu * mu;
        float s = __ldg(gamma + t) * rsqrtf(var + 1e-5f);
        ssc[t] = s;
        ssh[t] = __ldg(beta + t) - mu * s;
    }
    __syncthreads();

    int g = t >> 4, q = t & 15;
    int c0 = q * 4;
    float s0 = ssc[c0], s1 = ssc[c0 + 1], s2 = ssc[c0 + 2], s3 = ssc[c0 + 3];
    float h0 = ssh[c0], h1 = ssh[c0 + 1], h2 = ssh[c0 + 2], h3 = ssh[c0 + 3];

    float4 m = make_float4(0.f, 0.f, 0.f, 0.f);
    #pragma unroll
    for (int p = 0; p < 4; p++) {
        int row = b * 64 + p * 16 + g;
        float4 v = *(const float4*)(g_z2 + (size_t)row * DD + c0);
        v.x = fmaxf(fmaf(v.x, s0, h0), 0.f);
        v.y = fmaxf(fmaf(v.y, s1, h1), 0.f);
        v.z = fmaxf(fmaf(v.z, s2, h2), 0.f);
        v.w = fmaxf(fmaf(v.w, s3, h3), 0.f);
        if (!LAST) *(float4*)(g_h + (size_t)row * DD + c0) = v;
        m.x = fmaxf(m.x, v.x); m.y = fmaxf(m.y, v.y);
        m.z = fmaxf(m.z, v.z); m.w = fmaxf(m.w, v.w);
    }
    red[g * DD + c0 + 0] = m.x; red[g * DD + c0 + 1] = m.y;
    red[g * DD + c0 + 2] = m.z; red[g * DD + c0 + 3] = m.w;
    __syncthreads();

    if (t < DD) {
        float mv = red[t];
        #pragma unroll
        for (int gg = 1; gg < 16; gg++) mv = fmaxf(mv, red[gg * DD + t]);
        int sA = __ldg(n2s + b * 64), sB = __ldg(n2s + b * 64 + 63);
        if (sA == sB) {
            unsigned* p = (unsigned*)(out + (size_t)sA * 128 + layer * 64 + t);
            asm volatile("red.global.max.u32 [%0], %1;"
                         :: "l"(p), "r"(__float_as_uint(mv)) : "memory");
        } else {
            // correctness fallback: per-row segment max (recompute bn on the fly)
            for (int r = 0; r < 64; r++) {
                int seg = __ldg(n2s + b * 64 + r);
                float zv = g_z2[((size_t)b * 64 + r) * DD + t];
                float v = fmaxf(fmaf(zv, ssc[t], ssh[t]), 0.f);
                unsigned* p = (unsigned*)(out + (size_t)seg * 128 + layer * 64 + t);
                asm volatile("red.global.max.u32 [%0], %1;"
                             :: "l"(p), "r"(__float_as_uint(v)) : "memory");
            }
        }
    }
}

// ---------------------------------------------------------------------------
extern "C" void kernel_launch(void* const* d_in, const int* in_sizes, int n_in,
                              void* d_out, int out_size) {
    const float* x   = (const float*)d_in[0];
    const int*   ei  = (const int*)d_in[1];
    const int*   n2s = (const int*)d_in[2];
    const float* eps = (const float*)d_in[3];
    const float* W1  = (const float*)d_in[4];
    const float* b1  = (const float*)d_in[5];
    const float* gm  = (const float*)d_in[6];
    const float* bm  = (const float*)d_in[7];
    const float* W2  = (const float*)d_in[8];
    const float* b2  = (const float*)d_in[9];
    const float* go  = (const float*)d_in[10];
    const float* bo  = (const float*)d_in[11];
    float* out = (float*)d_out;

    init_kernel<<<128, 256>>>(out);
    count_kernel<<<EE / 256, 256>>>(ei);
    scan1_kernel<<<NN / 256, 256>>>();
    scan2_kernel<<<1, 256>>>();
    fill_kernel<<<EE / 256, 256>>>(ei);

    for (int l = 0; l < 2; l++) {
        gather_kernel<<<NN / 16, 256>>>(x, eps, l);
        gemm_kernel<false><<<NN / 128, 128>>>(W1 + l * DD * DD, b1 + l * DD,
                                              nullptr, nullptr, l);
        gemm_kernel<true><<<NN / 128, 128>>>(W2 + l * DD * DD, b2 + l * DD,
                                             gm + l * DD, bm + l * DD, l);
        if (l == 0)
            apply_kernel<false><<<NN / 64, 256>>>(n2s, out, go, bo, 0);
        else
            apply_kernel<true><<<NN / 64, 256>>>(n2s, out, go + DD, bo + DD, 1);
    }
}